// round 3
// baseline (speedup 1.0000x reference)
#include <cuda_runtime.h>
#include <cuda_bf16.h>

#define S_LEN 2048
#define NHEAD 16
#define DHEAD 64
#define BM 64
#define BN 64
#define PAD 68   // shared-memory row stride in floats (16B-aligned, kills bank conflicts)

__global__ __launch_bounds__(256, 2)
void attn_fwd_kernel(const float* __restrict__ Q, const float* __restrict__ K,
                     const float* __restrict__ V, float* __restrict__ Out) {
    extern __shared__ float sm[];
    float* Qt = sm;                 // [DHEAD][PAD]  Qt[d][r] = Q[r][d]
    float* Kt = Qt + DHEAD * PAD;   // [DHEAD][PAD]  Kt[d][c] = K[c][d]
    float* Vs = Kt + DHEAD * PAD;   // [BN][PAD]     Vs[c][d] = V[c][d]
    float* Ps = Vs + BN * PAD;      // [BM][PAD]     Ps[r][c] = softmax probs

    const int qt = blockIdx.x;          // q tile index (rows qt*64 .. qt*64+63)
    const int bh = blockIdx.y;          // b*16 + h
    const int b  = bh >> 4;
    const int h  = bh & 15;

    const float* Qg = Q + ((size_t)bh * S_LEN + (size_t)qt * BM) * DHEAD;
    const float* Kg = K + (size_t)bh * S_LEN * DHEAD;
    const float* Vg = V + (size_t)bh * S_LEN * DHEAD;

    const int tid = threadIdx.x;
    const int tx  = tid & 15;           // 0..15 -> column group (c0 = 4*tx, d0 = 4*tx)
    const int ty  = tid >> 4;           // 0..15 -> row group    (r0 = 4*ty)
    const int r0  = ty << 2;
    const int c0  = tx << 2;
    const int qrow_base = qt * BM;

    // ---- Load Q tile, transposed into shared ----
    for (int i = tid; i < BM * (DHEAD / 4); i += 256) {
        int r  = i >> 4;                // row within tile
        int d4 = (i & 15) << 2;         // d offset (float4 granularity)
        float4 v4 = *(const float4*)(Qg + r * DHEAD + d4);
        Qt[(d4 + 0) * PAD + r] = v4.x;
        Qt[(d4 + 1) * PAD + r] = v4.y;
        Qt[(d4 + 2) * PAD + r] = v4.z;
        Qt[(d4 + 3) * PAD + r] = v4.w;
    }

    float o[4][4];
    float m_run[4], l_run[4];
    #pragma unroll
    for (int i = 0; i < 4; i++) {
        m_run[i] = -1e30f;
        l_run[i] = 0.f;
        #pragma unroll
        for (int j = 0; j < 4; j++) o[i][j] = 0.f;
    }

    const float scale = 0.125f;  // 1/sqrt(64)

    for (int kt = 0; kt <= qt; kt++) {
        __syncthreads();  // prior iteration's GEMM2 readers done (also covers Qt on iter 0)

        // ---- Load K tile (transposed) and V tile (natural) ----
        const float* Kgt = Kg + (size_t)kt * BN * DHEAD;
        const float* Vgt = Vg + (size_t)kt * BN * DHEAD;
        for (int i = tid; i < BN * (DHEAD / 4); i += 256) {
            int c  = i >> 4;
            int d4 = (i & 15) << 2;
            float4 kv = *(const float4*)(Kgt + c * DHEAD + d4);
            Kt[(d4 + 0) * PAD + c] = kv.x;
            Kt[(d4 + 1) * PAD + c] = kv.y;
            Kt[(d4 + 2) * PAD + c] = kv.z;
            Kt[(d4 + 3) * PAD + c] = kv.w;
            float4 vv = *(const float4*)(Vgt + c * DHEAD + d4);
            *(float4*)(Vs + c * PAD + d4) = vv;
        }
        __syncthreads();

        // ---- GEMM1: s[r][c] = sum_d Qt[d][r] * Kt[d][c] ----
        float s[4][4];
        #pragma unroll
        for (int i = 0; i < 4; i++)
            #pragma unroll
            for (int j = 0; j < 4; j++) s[i][j] = 0.f;

        #pragma unroll 8
        for (int d = 0; d < DHEAD; d++) {
            float4 qf = *(const float4*)(Qt + d * PAD + r0);
            float4 kf = *(const float4*)(Kt + d * PAD + c0);
            float qa[4] = {qf.x, qf.y, qf.z, qf.w};
            float ka[4] = {kf.x, kf.y, kf.z, kf.w};
            #pragma unroll
            for (int i = 0; i < 4; i++)
                #pragma unroll
                for (int j = 0; j < 4; j++)
                    s[i][j] += qa[i] * ka[j];
        }

        // ---- Scale + causal mask (matches reference: scale first, then -10000) ----
        const bool diag = (kt == qt);
        #pragma unroll
        for (int i = 0; i < 4; i++) {
            int gr = qrow_base + r0 + i;
            #pragma unroll
            for (int j = 0; j < 4; j++) {
                float val = s[i][j] * scale;
                if (diag) {
                    int gc = kt * BN + c0 + j;
                    if (gc > gr) val = -10000.0f;
                }
                s[i][j] = val;
            }
        }

        // ---- Online softmax per row (reduce across the 16-lane row group) ----
        #pragma unroll
        for (int i = 0; i < 4; i++) {
            float mx = fmaxf(fmaxf(s[i][0], s[i][1]), fmaxf(s[i][2], s[i][3]));
            #pragma unroll
            for (int off = 8; off >= 1; off >>= 1)
                mx = fmaxf(mx, __shfl_xor_sync(0xffffffffu, mx, off, 16));
            float m_new = fmaxf(m_run[i], mx);
            float corr  = __expf(m_run[i] - m_new);
            float psum = 0.f;
            #pragma unroll
            for (int j = 0; j < 4; j++) {
                float p = __expf(s[i][j] - m_new);
                s[i][j] = p;
                psum += p;
            }
            #pragma unroll
            for (int off = 8; off >= 1; off >>= 1)
                psum += __shfl_xor_sync(0xffffffffu, psum, off, 16);
            l_run[i] = l_run[i] * corr + psum;
            m_run[i] = m_new;
            #pragma unroll
            for (int j = 0; j < 4; j++) o[i][j] *= corr;
            *(float4*)(Ps + (r0 + i) * PAD + c0) =
                make_float4(s[i][0], s[i][1], s[i][2], s[i][3]);
        }
        __syncthreads();

        // ---- GEMM2: o[r][d] += Ps[r][c] * Vs[c][d] ----
        #pragma unroll 8
        for (int c = 0; c < BN; c++) {
            float4 vf = *(const float4*)(Vs + c * PAD + c0);
            float va[4] = {vf.x, vf.y, vf.z, vf.w};
            float pa[4];
            #pragma unroll
            for (int i = 0; i < 4; i++) pa[i] = Ps[(r0 + i) * PAD + c];
            #pragma unroll
            for (int i = 0; i < 4; i++)
                #pragma unroll
                for (int j = 0; j < 4; j++)
                    o[i][j] += pa[i] * va[j];
        }
    }

    // ---- Epilogue: normalize and write out[b][s][h*64 + d] ----
    #pragma unroll
    for (int i = 0; i < 4; i++) {
        float inv = 1.f / l_run[i];
        int srow = qrow_base + r0 + i;
        float* op = Out + ((size_t)b * S_LEN + srow) * (NHEAD * DHEAD)
                        + h * DHEAD + c0;
        *(float4*)op = make_float4(o[i][0] * inv, o[i][1] * inv,
                                   o[i][2] * inv, o[i][3] * inv);
    }
}

extern "C" void kernel_launch(void* const* d_in, const int* in_sizes, int n_in,
                              void* d_out, int out_size) {
    (void)in_sizes; (void)n_in; (void)out_size;
    const float* q = (const float*)d_in[0];
    const float* k = (const float*)d_in[1];
    const float* v = (const float*)d_in[2];
    float* out = (float*)d_out;

    const int smem_bytes = 4 * DHEAD * PAD * sizeof(float);  // 69632 B
    cudaFuncSetAttribute(attn_fwd_kernel,
                         cudaFuncAttributeMaxDynamicSharedMemorySize, smem_bytes);

    dim3 grid(S_LEN / BM, 4 * NHEAD);   // (32, 64)
    attn_fwd_kernel<<<grid, 256, smem_bytes>>>(q, k, v, out);
}

// round 4
// speedup vs baseline: 3.1571x; 3.1571x over previous
#include <cuda_runtime.h>

#define S_LEN 2048
#define NHEAD 16
#define DHEAD 64
#define BM 64
#define BN 64
#define KS_STRIDE 68   // banks: 4g+t4  -> conflict-free B loads for GEMM1
#define VS_STRIDE 72   // banks: 8t4+g  -> conflict-free B loads for GEMM2
#define PS_STRIDE 68   // banks: 4g+t4  -> conflict-free A loads for GEMM2

__device__ __forceinline__ unsigned f2tf(float x) {
    unsigned y;
    asm("cvt.rna.tf32.f32 %0, %1;" : "=r"(y) : "f"(x));
    return y;
}

__device__ __forceinline__ void mma_tf32(float& d0, float& d1, float& d2, float& d3,
                                         unsigned a0, unsigned a1, unsigned a2, unsigned a3,
                                         unsigned b0, unsigned b1) {
    asm volatile("mma.sync.aligned.m16n8k8.row.col.f32.tf32.tf32.f32 "
                 "{%0,%1,%2,%3}, {%4,%5,%6,%7}, {%8,%9}, {%0,%1,%2,%3};"
                 : "+f"(d0), "+f"(d1), "+f"(d2), "+f"(d3)
                 : "r"(a0), "r"(a1), "r"(a2), "r"(a3), "r"(b0), "r"(b1));
}

__global__ __launch_bounds__(128, 2)
void attn_tc_kernel(const float* __restrict__ Q, const float* __restrict__ K,
                    const float* __restrict__ V, float* __restrict__ Out) {
    extern __shared__ float sm[];
    float* Ks = sm;                         // [64][KS_STRIDE] tf32 bits (also Q staging)
    float* Vs = Ks + BN * KS_STRIDE;        // [64][VS_STRIDE] tf32 bits
    float* Ps = Vs + BN * VS_STRIDE;        // [64][PS_STRIDE] tf32 bits (per-warp 16-row slabs)

    const int qt = blockIdx.x;
    const int bh = blockIdx.y;
    const int b  = bh >> 4;
    const int h  = bh & 15;

    const float* Qg = Q + ((size_t)bh * S_LEN + (size_t)qt * BM) * DHEAD;
    const float* Kg = K + (size_t)bh * S_LEN * DHEAD;
    const float* Vg = V + (size_t)bh * S_LEN * DHEAD;

    const int tid  = threadIdx.x;
    const int warp = tid >> 5;
    const int lane = tid & 31;
    const int g    = lane >> 2;   // groupID   (0..7)
    const int t4   = lane & 3;    // thread-in-group
    const int r0w  = warp << 4;   // warp's row slab base within tile
    const int qrow = qt * BM;

    // ---- Stage Q tile into shared (raw fp32), then pull A-fragments into regs ----
    #pragma unroll
    for (int it = 0; it < 8; it++) {
        int i  = tid + it * 128;
        int r  = i >> 4;
        int d4 = (i & 15) << 2;
        *(float4*)(Ks + r * KS_STRIDE + d4) = *(const float4*)(Qg + r * DHEAD + d4);
    }
    __syncthreads();

    unsigned qa[8][4];
    {
        const float* q0 = Ks + (r0w + g) * KS_STRIDE;
        const float* q1 = Ks + (r0w + g + 8) * KS_STRIDE;
        #pragma unroll
        for (int ks = 0; ks < 8; ks++) {
            qa[ks][0] = f2tf(0.125f * q0[t4 + 8 * ks]);
            qa[ks][1] = f2tf(0.125f * q1[t4 + 8 * ks]);
            qa[ks][2] = f2tf(0.125f * q0[t4 + 4 + 8 * ks]);
            qa[ks][3] = f2tf(0.125f * q1[t4 + 4 + 8 * ks]);
        }
    }

    float o[8][4];
    #pragma unroll
    for (int nt = 0; nt < 8; nt++)
        #pragma unroll
        for (int e = 0; e < 4; e++) o[nt][e] = 0.f;

    float m0 = -1e30f, m1 = -1e30f, l0 = 0.f, l1 = 0.f;
    const int row0 = qrow + r0w + g;
    const int row1 = row0 + 8;
    float* Psw = Ps + r0w * PS_STRIDE;

    for (int kt = 0; kt <= qt; kt++) {
        __syncthreads();  // prior readers of Ks/Vs done (covers qa extraction on iter 0)

        // ---- Stage K, V tiles (convert to tf32 once here) ----
        const float* Kgt = Kg + (size_t)kt * BN * DHEAD;
        const float* Vgt = Vg + (size_t)kt * BN * DHEAD;
        #pragma unroll
        for (int it = 0; it < 8; it++) {
            int i  = tid + it * 128;
            int r  = i >> 4;
            int d4 = (i & 15) << 2;
            float4 kk = *(const float4*)(Kgt + r * DHEAD + d4);
            float4 vv = *(const float4*)(Vgt + r * DHEAD + d4);
            *(float4*)(Ks + r * KS_STRIDE + d4) = make_float4(
                __uint_as_float(f2tf(kk.x)), __uint_as_float(f2tf(kk.y)),
                __uint_as_float(f2tf(kk.z)), __uint_as_float(f2tf(kk.w)));
            *(float4*)(Vs + r * VS_STRIDE + d4) = make_float4(
                __uint_as_float(f2tf(vv.x)), __uint_as_float(f2tf(vv.y)),
                __uint_as_float(f2tf(vv.z)), __uint_as_float(f2tf(vv.w)));
        }
        __syncthreads();

        // ---- GEMM1: S = (Q*scale) K^T   (A in regs, B from Ks) ----
        float s[8][4];
        #pragma unroll
        for (int nt = 0; nt < 8; nt++) {
            s[nt][0] = 0.f; s[nt][1] = 0.f; s[nt][2] = 0.f; s[nt][3] = 0.f;
            const float* kb = Ks + (g + 8 * nt) * KS_STRIDE + t4;
            #pragma unroll
            for (int ks = 0; ks < 8; ks++) {
                unsigned b0 = __float_as_uint(kb[8 * ks]);
                unsigned b1 = __float_as_uint(kb[8 * ks + 4]);
                mma_tf32(s[nt][0], s[nt][1], s[nt][2], s[nt][3],
                         qa[ks][0], qa[ks][1], qa[ks][2], qa[ks][3], b0, b1);
            }
        }

        // ---- Causal mask (diagonal tile only) ----
        if (kt == qt) {
            const int colb = kt * BN + 2 * t4;
            #pragma unroll
            for (int nt = 0; nt < 8; nt++) {
                int c0 = colb + 8 * nt;
                int c1 = c0 + 1;
                if (c0 > row0) s[nt][0] = -10000.0f;
                if (c1 > row0) s[nt][1] = -10000.0f;
                if (c0 > row1) s[nt][2] = -10000.0f;
                if (c1 > row1) s[nt][3] = -10000.0f;
            }
        }

        // ---- Online softmax (2 rows per thread) ----
        float mx0 = -1e30f, mx1 = -1e30f;
        #pragma unroll
        for (int nt = 0; nt < 8; nt++) {
            mx0 = fmaxf(mx0, fmaxf(s[nt][0], s[nt][1]));
            mx1 = fmaxf(mx1, fmaxf(s[nt][2], s[nt][3]));
        }
        mx0 = fmaxf(mx0, __shfl_xor_sync(0xffffffffu, mx0, 1));
        mx0 = fmaxf(mx0, __shfl_xor_sync(0xffffffffu, mx0, 2));
        mx1 = fmaxf(mx1, __shfl_xor_sync(0xffffffffu, mx1, 1));
        mx1 = fmaxf(mx1, __shfl_xor_sync(0xffffffffu, mx1, 2));

        float mn0 = fmaxf(m0, mx0), mn1 = fmaxf(m1, mx1);
        float cr0 = __expf(m0 - mn0), cr1 = __expf(m1 - mn1);

        float sum0 = 0.f, sum1 = 0.f;
        #pragma unroll
        for (int nt = 0; nt < 8; nt++) {
            float p0 = __expf(s[nt][0] - mn0);
            float p1 = __expf(s[nt][1] - mn0);
            float p2 = __expf(s[nt][2] - mn1);
            float p3 = __expf(s[nt][3] - mn1);
            sum0 += p0 + p1;
            sum1 += p2 + p3;
            int col = 8 * nt + 2 * t4;
            *(float2*)(Psw + g * PS_STRIDE + col) =
                make_float2(__uint_as_float(f2tf(p0)), __uint_as_float(f2tf(p1)));
            *(float2*)(Psw + (g + 8) * PS_STRIDE + col) =
                make_float2(__uint_as_float(f2tf(p2)), __uint_as_float(f2tf(p3)));
        }
        sum0 += __shfl_xor_sync(0xffffffffu, sum0, 1);
        sum0 += __shfl_xor_sync(0xffffffffu, sum0, 2);
        sum1 += __shfl_xor_sync(0xffffffffu, sum1, 1);
        sum1 += __shfl_xor_sync(0xffffffffu, sum1, 2);

        l0 = l0 * cr0 + sum0;
        l1 = l1 * cr1 + sum1;
        m0 = mn0; m1 = mn1;

        #pragma unroll
        for (int nt = 0; nt < 8; nt++) {
            o[nt][0] *= cr0; o[nt][1] *= cr0;
            o[nt][2] *= cr1; o[nt][3] *= cr1;
        }
        __syncwarp();  // Ps writes visible to whole warp (P is warp-private)

        // ---- GEMM2: O += P V   (A from Ps, B from Vs) ----
        #pragma unroll
        for (int ks = 0; ks < 8; ks++) {
            unsigned a0 = __float_as_uint(Psw[g * PS_STRIDE + t4 + 8 * ks]);
            unsigned a1 = __float_as_uint(Psw[(g + 8) * PS_STRIDE + t4 + 8 * ks]);
            unsigned a2 = __float_as_uint(Psw[g * PS_STRIDE + t4 + 4 + 8 * ks]);
            unsigned a3 = __float_as_uint(Psw[(g + 8) * PS_STRIDE + t4 + 4 + 8 * ks]);
            const float* vb = Vs + (t4 + 8 * ks) * VS_STRIDE + g;
            #pragma unroll
            for (int nt = 0; nt < 8; nt++) {
                unsigned b0 = __float_as_uint(vb[8 * nt]);
                unsigned b1 = __float_as_uint(vb[4 * VS_STRIDE + 8 * nt]);
                mma_tf32(o[nt][0], o[nt][1], o[nt][2], o[nt][3],
                         a0, a1, a2, a3, b0, b1);
            }
        }
    }

    // ---- Epilogue: normalize, write Out[b][s][h*64 + d] ----
    float inv0 = 1.f / l0;
    float inv1 = 1.f / l1;
    float* Op0 = Out + ((size_t)b * S_LEN + row0) * (NHEAD * DHEAD) + h * DHEAD;
    float* Op1 = Out + ((size_t)b * S_LEN + row1) * (NHEAD * DHEAD) + h * DHEAD;
    #pragma unroll
    for (int nt = 0; nt < 8; nt++) {
        int col = 8 * nt + 2 * t4;
        *(float2*)(Op0 + col) = make_float2(o[nt][0] * inv0, o[nt][1] * inv0);
        *(float2*)(Op1 + col) = make_float2(o[nt][2] * inv1, o[nt][3] * inv1);
    }
}

extern "C" void kernel_launch(void* const* d_in, const int* in_sizes, int n_in,
                              void* d_out, int out_size) {
    (void)in_sizes; (void)n_in; (void)out_size;
    const float* q = (const float*)d_in[0];
    const float* k = (const float*)d_in[1];
    const float* v = (const float*)d_in[2];
    float* out = (float*)d_out;

    const int smem_bytes = (BN * KS_STRIDE + BN * VS_STRIDE + BM * PS_STRIDE) * sizeof(float);
    cudaFuncSetAttribute(attn_tc_kernel,
                         cudaFuncAttributeMaxDynamicSharedMemorySize, smem_bytes);

    dim3 grid(S_LEN / BM, 4 * NHEAD);   // (32, 64)
    attn_tc_kernel<<<grid, 128, smem_bytes>>>(q, k, v, out);
}